// round 15
// baseline (speedup 1.0000x reference)
#include <cuda_runtime.h>
#include <cuda_fp16.h>
#include <cstdint>

#define HW 4096
#define DDIM 64
#define NSLICE 256           // total K slices of 16
#define NCH 32               // chunks (128 floats of K each)
#define SROW 528             // smem row stride (bank-skewed, 16B-aligned)
#define BUFSZ (64 * SROW)    // 33792 per buffer
#define MBAR_OFF (2 * BUFSZ) // 67584
#define SMEM_BYTES (MBAR_OFF + 16)
#define CS_STRIDE 66

// B fragments, lane-major: g_fp[slice][q][lane][4 x b32]; uint4 index = s*128 + q*32 + l
// ISA->real K map (per 32-block): real = 8*(l&3) + 4*(s&1) + 2*pair + t
__device__ uint32_t g_fp[NSLICE * 4 * 32 * 4];

// ---------------------------------------------------------------------------
// Kernel 1: build packed B fragments of f[m,d] = cos(8pi*(w0*gx + w1*gy + b))
// ---------------------------------------------------------------------------
__global__ void pos_enc_kernel(const float* __restrict__ w,
                               const float* __restrict__ bias) {
    int idx = blockIdx.x * blockDim.x + threadIdx.x;
    if (idx >= NSLICE * 512) return;
    int c    = idx & 3;
    int l    = (idx >> 2) & 31;
    int q    = (idx >> 7) & 3;
    int gs   = idx >> 9;
    int j    = q * 2 + (c >> 1);
    int pair = c & 1;
    int d    = j * 8 + (l >> 2);
    int m0   = (gs >> 1) * 32 + ((l & 3) << 3) + ((gs & 1) << 2) + (pair << 1);
    float w0 = w[2 * d], w1 = w[2 * d + 1], bd = bias[d];
    float v[2];
#pragma unroll
    for (int t = 0; t < 2; t++) {
        int m = m0 + t;
        int x = m & 63, y = m >> 6;
        float gx = (float)(2 * x - 63) * (1.0f / 64.0f);
        float gy = (float)(2 * y - 63) * (1.0f / 64.0f);
        v[t] = cosf(25.132741228718345f * fmaf(w0, gx, fmaf(w1, gy, bd)));
    }
    __half2 h = __floats2half2_rn(v[0], v[1]);
    g_fp[idx] = *reinterpret_cast<uint32_t*>(&h);
}

// ---------------------------------------------------------------------------
#define E2PH(dst, x, y)                                                         \
    do {                                                                        \
        float _fa = (x) * 1.4426950408889634f;                                  \
        float _fb = (y) * 1.4426950408889634f;                                  \
        asm("cvt.rn.f16x2.f32 %0, %1, %2;" : "=r"(dst) : "f"(_fb), "f"(_fa));   \
        asm("ex2.approx.f16x2 %0, %0;" : "+r"(dst));                            \
    } while (0)

#define MMA(dst, a0, a1, a2, a3, b0, b1)                                        \
    asm volatile("mma.sync.aligned.m16n8k16.row.col.f32.f16.f16.f32 "           \
                 "{%0,%1,%2,%3},{%4,%5,%6,%7},{%8,%9},{%0,%1,%2,%3};"           \
                 : "+f"(dst[0]), "+f"(dst[1]), "+f"(dst[2]), "+f"(dst[3])       \
                 : "r"(a0), "r"(a1), "r"(a2), "r"(a3), "r"(b0), "r"(b1))

#define LDSA(v, addr)                                                           \
    asm volatile("ld.shared.v4.f32 {%0,%1,%2,%3}, [%4];"                        \
                 : "=f"(v.x), "=f"(v.y), "=f"(v.z), "=f"(v.w) : "r"(addr))

#define MBAR_WAIT(addr, parity)                                                 \
    asm volatile("{\n .reg .pred P;\n"                                          \
                 "WL%=:\n mbarrier.try_wait.parity.acquire.cta.shared::cta.b64 "\
                 "P, [%0], %1, 0x989680;\n"                                     \
                 " @P bra.uni WD%=;\n bra.uni WL%=;\n WD%=:\n}"                 \
                 :: "r"(addr), "r"(parity) : "memory")

// Issue chunk c into buffer b: expect_tx + 64 x 512B bulk copies (tid0 only)
#define ISSUE(c, b)                                                             \
    do {                                                                        \
        uint32_t _mb = smem_u + MBAR_OFF + (b) * 8;                             \
        asm volatile("mbarrier.arrive.expect_tx.shared.b64 _, [%0], %1;"        \
                     :: "r"(_mb), "r"(32768u) : "memory");                      \
        uint32_t _d0 = smem_u + (b) * BUFSZ;                                    \
        const char* _s0 = gA + (size_t)(c) * 512;                               \
        _Pragma("unroll 16")                                                    \
        for (int _r = 0; _r < 64; _r++)                                         \
            asm volatile("cp.async.bulk.shared::cluster.global"                 \
                         ".mbarrier::complete_tx::bytes [%0], [%1], 512, [%2];" \
                         :: "r"(_d0 + _r * SROW),                               \
                            "l"(_s0 + (size_t)_r * (HW * 4)), "r"(_mb)         \
                         : "memory");                                           \
    } while (0)

// One 16-slice: on-demand B (global slice s), f16x2 exp, 9 MMAs
#define HALF_STAGE(sidx, rl, rh)                                                \
    do {                                                                        \
        const uint4* _bp = pB + (size_t)(sidx) * 128;                           \
        uint4 B0 = __ldg(_bp);      uint4 B1 = __ldg(_bp + 32);                 \
        uint4 B2 = __ldg(_bp + 64); uint4 B3 = __ldg(_bp + 96);                 \
        uint32_t ra0, ra1, ra2, ra3;                                            \
        E2PH(ra0, rl.x, rl.y);                                                  \
        E2PH(ra2, rl.z, rl.w);                                                  \
        E2PH(ra1, rh.x, rh.y);                                                  \
        E2PH(ra3, rh.z, rh.w);                                                  \
        MMA(acc[0], ra0, ra1, ra2, ra3, B0.x, B0.y);                            \
        MMA(acc[1], ra0, ra1, ra2, ra3, B0.z, B0.w);                            \
        MMA(acc[2], ra0, ra1, ra2, ra3, B1.x, B1.y);                            \
        MMA(acc[3], ra0, ra1, ra2, ra3, B1.z, B1.w);                            \
        MMA(acc[4], ra0, ra1, ra2, ra3, B2.x, B2.y);                            \
        MMA(acc[5], ra0, ra1, ra2, ra3, B2.z, B2.w);                            \
        MMA(acc[6], ra0, ra1, ra2, ra3, B3.x, B3.y);                            \
        MMA(acc[7], ra0, ra1, ra2, ra3, B3.z, B3.w);                            \
        MMA(acc[8], ra0, ra1, ra2, ra3, bz, bz);                                \
    } while (0)

// One 32-float block: 4 LDS.128 + 2 slices
#define BLOCK(bq, blk, c)                                                       \
    do {                                                                        \
        uint32_t _a = abase + (bq) * BUFSZ + (blk) * 128;                       \
        float4 A0, A1, A2, A3;                                                  \
        LDSA(A0, _a);                                                           \
        LDSA(A1, _a + 16);                                                      \
        LDSA(A2, _a + 8 * SROW);                                                \
        LDSA(A3, _a + 8 * SROW + 16);                                           \
        const int _sb = (c) * 8 + kh * 4 + 2 * (blk);                           \
        HALF_STAGE(_sb,     A0, A2);                                            \
        HALF_STAGE(_sb + 1, A1, A3);                                            \
    } while (0)

// ---------------------------------------------------------------------------
// Kernel 2: 8 warps = 4 row-groups x 2 K-halves (within chunk). 64 rows/CTA.
// A via cp.async.bulk double-buffered smem (32KB chunks, mbarrier-paced);
// B on-demand LDG; f16x2 exp; Z via 9th MMA.
// ---------------------------------------------------------------------------
__global__ __launch_bounds__(256, 2)
void gp_kernel(const float* __restrict__ sim, float* __restrict__ out) {
    extern __shared__ char smem[];
    uint32_t smem_u;
    asm("{ .reg .u64 t; cvta.to.shared.u64 t, %1; cvt.u32.u64 %0, t; }"
        : "=r"(smem_u) : "l"(smem));

    const int tid = threadIdx.x;
    const int l   = tid & 31;
    const int w   = tid >> 5;
    const int wm  = w & 3;        // row group
    const int kh  = w >> 2;       // K half (within chunk)
    const int bb  = blockIdx.y;
    const int row0 = blockIdx.x * 64;

    if (tid == 0) {
        asm volatile("mbarrier.init.shared.b64 [%0], 1;" :: "r"(smem_u + MBAR_OFF) : "memory");
        asm volatile("mbarrier.init.shared.b64 [%0], 1;" :: "r"(smem_u + MBAR_OFF + 8) : "memory");
    }
    __syncthreads();

    const char* gA = (const char*)(sim + ((size_t)bb * HW + row0) * HW);
    const uint4* pB = ((const uint4*)g_fp) + l;
    const uint32_t abase = smem_u + (wm * 16 + (l >> 2)) * SROW + kh * 256 + (l & 3) * 32;

    float acc[9][4];
#pragma unroll
    for (int i = 0; i < 9; i++)
#pragma unroll
        for (int k = 0; k < 4; k++) acc[i][k] = 0.0f;

    const uint32_t bz = (l < 4) ? 0x3C003C00u : 0u;  // ones in B col n=0

    if (tid == 0) { ISSUE(0, 0); ISSUE(1, 1); }

    int ph0 = 0, ph1 = 0;
#pragma unroll 1
    for (int c = 0; c < NCH; c++) {
        const int b = c & 1;
        if (b == 0) { MBAR_WAIT(smem_u + MBAR_OFF,     ph0); ph0 ^= 1; }
        else        { MBAR_WAIT(smem_u + MBAR_OFF + 8, ph1); ph1 ^= 1; }
        BLOCK(b, 0, c);
        BLOCK(b, 1, c);
        __syncthreads();
        if (c + 2 < NCH && tid == 0) ISSUE(c + 2, b);
    }

    // ---- epilogue: merge K-halves via smem (reuse buffers), divide, store ----
    float* Cs = (float*)smem;                     // [64][CS_STRIDE] in buf0
    float* Zs = (float*)(smem + BUFSZ);           // in buf1
    float* Zr = Zs + 64;

    const int lr = wm * 16 + (l >> 2);
    if (kh == 0) {
#pragma unroll
        for (int j = 0; j < 8; j++) {
            const int c0 = j * 8 + (l & 3) * 2;
            *(float2*)&Cs[lr * CS_STRIDE + c0]       = make_float2(acc[j][0], acc[j][1]);
            *(float2*)&Cs[(lr + 8) * CS_STRIDE + c0] = make_float2(acc[j][2], acc[j][3]);
        }
        if ((l & 3) == 0) { Zs[lr] = acc[8][0]; Zs[lr + 8] = acc[8][2]; }
    }
    __syncthreads();
    if (kh == 1) {
#pragma unroll
        for (int j = 0; j < 8; j++) {
            const int c0 = j * 8 + (l & 3) * 2;
            Cs[lr * CS_STRIDE + c0]           += acc[j][0];
            Cs[lr * CS_STRIDE + c0 + 1]       += acc[j][1];
            Cs[(lr + 8) * CS_STRIDE + c0]     += acc[j][2];
            Cs[(lr + 8) * CS_STRIDE + c0 + 1] += acc[j][3];
        }
        if ((l & 3) == 0) { Zs[lr] += acc[8][0]; Zs[lr + 8] += acc[8][2]; }
    }
    __syncthreads();
    if (tid < 64) Zr[tid] = 1.0f / Zs[tid];
    __syncthreads();

    {
        const int d = tid >> 2, seg = tid & 3;
        float* go = out + ((size_t)(bb * DDIM + d)) * HW + row0 + seg * 16;
#pragma unroll
        for (int i = 0; i < 4; i++) {
            const int n = seg * 16 + i * 4;
            float4 o;
            o.x = Cs[(n + 0) * CS_STRIDE + d] * Zr[n + 0];
            o.y = Cs[(n + 1) * CS_STRIDE + d] * Zr[n + 1];
            o.z = Cs[(n + 2) * CS_STRIDE + d] * Zr[n + 2];
            o.w = Cs[(n + 3) * CS_STRIDE + d] * Zr[n + 3];
            *(float4*)(go + i * 4) = o;
        }
    }
}

// ---------------------------------------------------------------------------
extern "C" void kernel_launch(void* const* d_in, const int* in_sizes, int n_in,
                              void* d_out, int out_size) {
    const float* sim  = (const float*)d_in[0];  // [4, 4096, 4096] fp32
    const float* w    = (const float*)d_in[1];  // [64, 2] fp32
    const float* bias = (const float*)d_in[2];  // [64] fp32
    float* out = (float*)d_out;                 // [4, 64, 64, 64] fp32

    cudaFuncSetAttribute(gp_kernel, cudaFuncAttributeMaxDynamicSharedMemorySize, SMEM_BYTES);

    pos_enc_kernel<<<(NSLICE * 512 + 255) / 256, 256>>>(w, bias);

    dim3 grid(HW / 64, 4);
    gp_kernel<<<grid, 256, SMEM_BYTES>>>(sim, out);
}

// round 16
// speedup vs baseline: 1.4705x; 1.4705x over previous
#include <cuda_runtime.h>
#include <cuda_fp16.h>
#include <cstdint>

#define HW 4096
#define DDIM 64
#define NSLICE 256           // total K slices of 16
#define HSLICE 128           // slices per K-half
#define NCHK 32              // 64-float chunks per K-half
#define RSTR 272             // smem row stride (bank-skewed, 16B aligned)
#define BUFB (16 * RSTR)     // 4352 B per buffer (16 rows x 272)
#define RINGB (2 * BUFB)     // 8704 B per warp
#define SMEM_BYTES (8 * RINGB)   // 69632
#define CS_STRIDE 66

// B fragments, lane-major: g_fp[slice][q][lane][4 x b32]; uint4 index = s*128 + q*32 + l
// ISA->real K map (per 32-float block): real = 8*(l&3) + 4*(s&1) + 2*pair + t
__device__ uint32_t g_fp[NSLICE * 4 * 32 * 4];

// ---------------------------------------------------------------------------
// Kernel 1: build packed B fragments of f[m,d] = cos(8pi*(w0*gx + w1*gy + b))
// ---------------------------------------------------------------------------
__global__ void pos_enc_kernel(const float* __restrict__ w,
                               const float* __restrict__ bias) {
    int idx = blockIdx.x * blockDim.x + threadIdx.x;
    if (idx >= NSLICE * 512) return;
    int c    = idx & 3;
    int l    = (idx >> 2) & 31;
    int q    = (idx >> 7) & 3;
    int gs   = idx >> 9;
    int j    = q * 2 + (c >> 1);
    int pair = c & 1;
    int d    = j * 8 + (l >> 2);
    int m0   = (gs >> 1) * 32 + ((l & 3) << 3) + ((gs & 1) << 2) + (pair << 1);
    float w0 = w[2 * d], w1 = w[2 * d + 1], bd = bias[d];
    float v[2];
#pragma unroll
    for (int t = 0; t < 2; t++) {
        int m = m0 + t;
        int x = m & 63, y = m >> 6;
        float gx = (float)(2 * x - 63) * (1.0f / 64.0f);
        float gy = (float)(2 * y - 63) * (1.0f / 64.0f);
        v[t] = cosf(25.132741228718345f * fmaf(w0, gx, fmaf(w1, gy, bd)));
    }
    __half2 h = __floats2half2_rn(v[0], v[1]);
    g_fp[idx] = *reinterpret_cast<uint32_t*>(&h);
}

// ---------------------------------------------------------------------------
#define E2PH(dst, x, y)                                                         \
    do {                                                                        \
        float _fa = (x) * 1.4426950408889634f;                                  \
        float _fb = (y) * 1.4426950408889634f;                                  \
        asm("cvt.rn.f16x2.f32 %0, %1, %2;" : "=r"(dst) : "f"(_fb), "f"(_fa));   \
        asm("ex2.approx.f16x2 %0, %0;" : "+r"(dst));                            \
    } while (0)

#define MMA(dst, a0, a1, a2, a3, b0, b1)                                        \
    asm volatile("mma.sync.aligned.m16n8k16.row.col.f32.f16.f16.f32 "           \
                 "{%0,%1,%2,%3},{%4,%5,%6,%7},{%8,%9},{%0,%1,%2,%3};"           \
                 : "+f"(dst[0]), "+f"(dst[1]), "+f"(dst[2]), "+f"(dst[3])       \
                 : "r"(a0), "r"(a1), "r"(a2), "r"(a3), "r"(b0), "r"(b1))

#define LDSA(v, addr)                                                           \
    asm volatile("ld.shared.v4.f32 {%0,%1,%2,%3}, [%4];"                        \
                 : "=f"(v.x), "=f"(v.y), "=f"(v.z), "=f"(v.w) : "r"(addr))

// Warp-private chunk issue: 8 cp.async instrs, each = 2 rows x 256B contiguous
// (half-warp per row -> 256B bursts reach the MC in issue order).
#define ISSUEC(c, buf)                                                          \
    do {                                                                        \
        const char* _s = gsl + (size_t)(c) * 256;                               \
        uint32_t _d = dlane + (buf) * BUFB;                                     \
        _Pragma("unroll")                                                       \
        for (int _i = 0; _i < 8; _i++)                                          \
            asm volatile("cp.async.cg.shared.global [%0], [%1], 16;"            \
                         :: "r"(_d + _i * 2 * RSTR),                            \
                            "l"(_s + (size_t)_i * 2 * (HW * 4)) : "memory");    \
        asm volatile("cp.async.commit_group;" ::: "memory");                    \
    } while (0)

// One 16-slice: on-demand B, f16x2 exp, 9 MMAs (A from smem float4s)
#define HALF_STAGE(sidx, rl, rh)                                                \
    do {                                                                        \
        const uint4* _bp = pB + (size_t)(sidx) * 128;                           \
        uint4 B0 = __ldg(_bp);      uint4 B1 = __ldg(_bp + 32);                 \
        uint4 B2 = __ldg(_bp + 64); uint4 B3 = __ldg(_bp + 96);                 \
        uint32_t ra0, ra1, ra2, ra3;                                            \
        E2PH(ra0, rl.x, rl.y);                                                  \
        E2PH(ra2, rl.z, rl.w);                                                  \
        E2PH(ra1, rh.x, rh.y);                                                  \
        E2PH(ra3, rh.z, rh.w);                                                  \
        MMA(acc[0], ra0, ra1, ra2, ra3, B0.x, B0.y);                            \
        MMA(acc[1], ra0, ra1, ra2, ra3, B0.z, B0.w);                            \
        MMA(acc[2], ra0, ra1, ra2, ra3, B1.x, B1.y);                            \
        MMA(acc[3], ra0, ra1, ra2, ra3, B1.z, B1.w);                            \
        MMA(acc[4], ra0, ra1, ra2, ra3, B2.x, B2.y);                            \
        MMA(acc[5], ra0, ra1, ra2, ra3, B2.z, B2.w);                            \
        MMA(acc[6], ra0, ra1, ra2, ra3, B3.x, B3.y);                            \
        MMA(acc[7], ra0, ra1, ra2, ra3, B3.z, B3.w);                            \
        MMA(acc[8], ra0, ra1, ra2, ra3, bz, bz);                                \
    } while (0)

// One 32-float block from smem buffer: 4 LDS.128 + 2 slices
#define BLOCK(buf, blk, c)                                                      \
    do {                                                                        \
        uint32_t _a = abase + (buf) * BUFB + (blk) * 128;                       \
        float4 A0, A1, A2, A3;                                                  \
        LDSA(A0, _a);                                                           \
        LDSA(A1, _a + 16);                                                      \
        LDSA(A2, _a + 8 * RSTR);                                                \
        LDSA(A3, _a + 8 * RSTR + 16);                                           \
        const int _sb = (c) * 4 + 2 * (blk);                                    \
        HALF_STAGE(_sb,     A0, A2);                                            \
        HALF_STAGE(_sb + 1, A1, A3);                                            \
    } while (0)

// ---------------------------------------------------------------------------
// Kernel 2: 8 warps = 4 row-groups x 2 K-halves. Warp: 16 rows x 64 N x K=2048.
// Warp-private cp.async A ring (depth 2, 256B/row bursts, wait_group-paced,
// zero CTA barriers in mainloop). B on-demand LDG; f16x2 exp; Z via 9th MMA.
// ---------------------------------------------------------------------------
__global__ __launch_bounds__(256, 2)
void gp_kernel(const float* __restrict__ sim, float* __restrict__ out) {
    extern __shared__ char smem[];
    uint32_t smem_u;
    asm("{ .reg .u64 t; cvta.to.shared.u64 t, %1; cvt.u32.u64 %0, t; }"
        : "=r"(smem_u) : "l"(smem));

    const int tid = threadIdx.x;
    const int l   = tid & 31;
    const int w   = tid >> 5;
    const int wm  = w & 3;       // row group (16 rows)
    const int kh  = w >> 2;      // K half
    const int bb  = blockIdx.y;
    const int row0 = blockIdx.x * 64;

    // per-lane global source: row (l>>4) of each 2-row pair, 16B at (l&15)*16
    const char* gsl = (const char*)sim
        + ((size_t)(bb * HW + row0 + wm * 16 + (l >> 4)) * HW + kh * (HSLICE * 16)) * 4
        + (l & 15) * 16;
    const uint32_t ring  = smem_u + w * RINGB;
    const uint32_t dlane = ring + (l >> 4) * RSTR + (l & 15) * 16;
    const uint32_t abase = ring + (l >> 2) * RSTR + (l & 3) * 32;

    const uint4* pB = ((const uint4*)g_fp) + (size_t)kh * HSLICE * 128 + l;

    float acc[9][4];
#pragma unroll
    for (int i = 0; i < 9; i++)
#pragma unroll
        for (int k = 0; k < 4; k++) acc[i][k] = 0.0f;

    const uint32_t bz = (l < 4) ? 0x3C003C00u : 0u;  // ones in B col n=0

    ISSUEC(0, 0);
    ISSUEC(1, 1);

#pragma unroll 1
    for (int c = 0; c < NCHK; c++) {
        const int buf = c & 1;
        if (c < NCHK - 1) asm volatile("cp.async.wait_group 1;" ::: "memory");
        else              asm volatile("cp.async.wait_group 0;" ::: "memory");
        __syncwarp();
        BLOCK(buf, 0, c);
        BLOCK(buf, 1, c);
        if (c + 2 < NCHK) ISSUEC(c + 2, buf);
    }

    // ---- epilogue: merge K-halves (smem overlay), divide by Z, store ----
    __syncthreads();   // all ring reads done before overlay
    float* Cs = (float*)smem;                          // [64][CS_STRIDE]
    float* Zs = (float*)(smem + 64 * CS_STRIDE * 4);   // [64]
    float* Zr = Zs + 64;

    const int lr = wm * 16 + (l >> 2);
    if (kh == 0) {
#pragma unroll
        for (int j = 0; j < 8; j++) {
            const int c0 = j * 8 + (l & 3) * 2;
            *(float2*)&Cs[lr * CS_STRIDE + c0]       = make_float2(acc[j][0], acc[j][1]);
            *(float2*)&Cs[(lr + 8) * CS_STRIDE + c0] = make_float2(acc[j][2], acc[j][3]);
        }
        if ((l & 3) == 0) { Zs[lr] = acc[8][0]; Zs[lr + 8] = acc[8][2]; }
    }
    __syncthreads();
    if (kh == 1) {
#pragma unroll
        for (int j = 0; j < 8; j++) {
            const int c0 = j * 8 + (l & 3) * 2;
            Cs[lr * CS_STRIDE + c0]           += acc[j][0];
            Cs[lr * CS_STRIDE + c0 + 1]       += acc[j][1];
            Cs[(lr + 8) * CS_STRIDE + c0]     += acc[j][2];
            Cs[(lr + 8) * CS_STRIDE + c0 + 1] += acc[j][3];
        }
        if ((l & 3) == 0) { Zs[lr] += acc[8][0]; Zs[lr + 8] += acc[8][2]; }
    }
    __syncthreads();
    if (tid < 64) Zr[tid] = 1.0f / Zs[tid];
    __syncthreads();

    {
        const int d = tid >> 2, seg = tid & 3;
        float* go = out + ((size_t)(bb * DDIM + d)) * HW + row0 + seg * 16;
#pragma unroll
        for (int i = 0; i < 4; i++) {
            const int n = seg * 16 + i * 4;
            float4 o;
            o.x = Cs[(n + 0) * CS_STRIDE + d] * Zr[n + 0];
            o.y = Cs[(n + 1) * CS_STRIDE + d] * Zr[n + 1];
            o.z = Cs[(n + 2) * CS_STRIDE + d] * Zr[n + 2];
            o.w = Cs[(n + 3) * CS_STRIDE + d] * Zr[n + 3];
            *(float4*)(go + i * 4) = o;
        }
    }
}

// ---------------------------------------------------------------------------
extern "C" void kernel_launch(void* const* d_in, const int* in_sizes, int n_in,
                              void* d_out, int out_size) {
    const float* sim  = (const float*)d_in[0];  // [4, 4096, 4096] fp32
    const float* w    = (const float*)d_in[1];  // [64, 2] fp32
    const float* bias = (const float*)d_in[2];  // [64] fp32
    float* out = (float*)d_out;                 // [4, 64, 64, 64] fp32

    cudaFuncSetAttribute(gp_kernel, cudaFuncAttributeMaxDynamicSharedMemorySize, SMEM_BYTES);

    pos_enc_kernel<<<(NSLICE * 512 + 255) / 256, 256>>>(w, bias);

    dim3 grid(HW / 64, 4);
    gp_kernel<<<grid, 256, SMEM_BYTES>>>(sim, out);
}